// round 16
// baseline (speedup 1.0000x reference)
#include <cuda_runtime.h>
#include <cstdint>

#define NCONS 256                                  // consumer threads (8 warps)
#define THREADS (NCONS + 32)                       // + 1 producer warp = 288
#define CPB 256                                    // cells per chunk
#define TENSOR_CHUNK_BYTES (CPB * 30 * 4)          // 30720
#define HALF_TENSOR_BYTES (TENSOR_CHUNK_BYTES / 2) // 15360
#define STAGE_BYTES (2 * TENSOR_CHUNK_BYTES)       // 61440 (pred + targ)
#define STAGE_FLOATS (STAGE_BYTES / 4)
#define TENSOR_CHUNK_FLOATS (TENSOR_CHUNK_BYTES / 4)
#define NSTAGES 3
#define SMEM_BYTES (NSTAGES * STAGE_BYTES)         // 184320 -> 1 CTA/SM
#define MAX_BLOCKS 4096

__device__ float        g_partials[MAX_BLOCKS];
__device__ unsigned int g_ticket = 0;

extern __shared__ float smem_buf[];

__device__ __forceinline__ uint32_t smem_u32(const void* p) {
    return (uint32_t)__cvta_generic_to_shared(p);
}
__device__ __forceinline__ void mbar_init(uint32_t bar, uint32_t count) {
    asm volatile("mbarrier.init.shared.b64 [%0], %1;" :: "r"(bar), "r"(count) : "memory");
}
__device__ __forceinline__ void mbar_expect_tx(uint32_t bar, uint32_t bytes) {
    asm volatile("mbarrier.arrive.expect_tx.shared.b64 _, [%0], %1;"
                 :: "r"(bar), "r"(bytes) : "memory");
}
__device__ __forceinline__ void mbar_arrive(uint32_t bar) {
    asm volatile("mbarrier.arrive.release.cta.shared::cta.b64 _, [%0];"
                 :: "r"(bar) : "memory");
}
__device__ __forceinline__ void mbar_wait_acq(uint32_t bar, uint32_t phase) {
    uint32_t done;
    asm volatile(
        "{\n\t.reg .pred p;\n\t"
        "mbarrier.try_wait.parity.acquire.cta.shared::cta.b64 p, [%1], %2;\n\t"
        "selp.b32 %0, 1, 0, p;\n\t}"
        : "=r"(done) : "r"(bar), "r"(phase) : "memory");
    while (!done) {
        asm volatile(
            "{\n\t.reg .pred p;\n\t"
            "mbarrier.try_wait.parity.acquire.cta.shared::cta.b64 p, [%1], %2, 0x989680;\n\t"
            "selp.b32 %0, 1, 0, p;\n\t}"
            : "=r"(done) : "r"(bar), "r"(phase) : "memory");
    }
}
// Relaxed wait: producer only — its post-wait writes are async-proxy bulk copies.
__device__ __forceinline__ void mbar_wait_rlx(uint32_t bar, uint32_t phase) {
    uint32_t done;
    asm volatile(
        "{\n\t.reg .pred p;\n\t"
        "mbarrier.try_wait.parity.relaxed.cta.shared::cta.b64 p, [%1], %2, 0x989680;\n\t"
        "selp.b32 %0, 1, 0, p;\n\t}"
        : "=r"(done) : "r"(bar), "r"(phase) : "memory");
    while (!done) {
        asm volatile(
            "{\n\t.reg .pred p;\n\t"
            "mbarrier.try_wait.parity.relaxed.cta.shared::cta.b64 p, [%1], %2, 0x989680;\n\t"
            "selp.b32 %0, 1, 0, p;\n\t}"
            : "=r"(done) : "r"(bar), "r"(phase) : "memory");
    }
}
__device__ __forceinline__ void bulk_cp(uint32_t dst_smem, const void* src_gmem,
                                        uint32_t bytes, uint32_t bar) {
    asm volatile(
        "cp.async.bulk.shared::cluster.global.mbarrier::complete_tx::bytes "
        "[%0], [%1], %2, [%3];"
        :: "r"(dst_smem), "l"(src_gmem), "r"(bytes), "r"(bar) : "memory");
}

__device__ __forceinline__ float cell_loss_reg(const float* __restrict__ P,
                                               const float* __restrict__ T)
{
    const float inv14 = 1.0f / 14.0f;

    const float conf_t = T[4];
    const float coo = (conf_t > 0.0f) ? 1.0f : 0.0f;
    const float noo = (conf_t == 0.0f) ? 1.0f : 0.0f;

    const float tcx = T[0] * inv14;
    const float tcy = T[1] * inv14;
    const float tx1 = tcx - 0.5f * T[2];
    const float ty1 = tcy - 0.5f * T[3];
    const float tx2 = tcx + 0.5f * T[2];
    const float ty2 = tcy + 0.5f * T[3];
    const float ta = (tx2 - tx1) * (ty2 - ty1);

    float iou[2];
    #pragma unroll
    for (int b = 0; b < 2; b++) {
        const float* B = P + b * 5;
        const float pcx = B[0] * inv14;
        const float pcy = B[1] * inv14;
        const float px1 = pcx - 0.5f * B[2];
        const float py1 = pcy - 0.5f * B[3];
        const float px2 = pcx + 0.5f * B[2];
        const float py2 = pcy + 0.5f * B[3];
        const float ltx = fmaxf(px1, tx1);
        const float lty = fmaxf(py1, ty1);
        const float rbx = fminf(px2, tx2);
        const float rby = fminf(py2, ty2);
        const float w = fmaxf(rbx - ltx, 0.0f);
        const float h = fmaxf(rby - lty, 0.0f);
        const float inter = w * h;
        const float pa = (px2 - px1) * (py2 - py1);
        iou[b] = __fdividef(inter, pa + ta - inter);
    }

    const int r = (iou[1] > iou[0]) ? 1 : 0;   // argmax: first max wins
    const int ro = r * 5, nro = (1 - r) * 5;
    const float max_iou = (iou[1] > iou[0]) ? iou[1] : iou[0];

    const float dx = P[ro + 0] - T[0];
    const float dy = P[ro + 1] - T[1];
    const float dsw = sqrtf(P[ro + 2]) - sqrtf(T[2]);
    const float dsh = sqrtf(P[ro + 3]) - sqrtf(T[3]);
    const float loc = dx * dx + dy * dy + dsw * dsw + dsh * dsh;

    const float dcc = P[ro + 4] - max_iou;
    const float contain = dcc * dcc;
    const float ncl = P[nro + 4] * P[nro + 4];

    const float d4 = P[4] - T[4];
    const float d9 = P[9] - T[9];
    const float noobj = d4 * d4 + d9 * d9;

    float cls = 0.0f;
    #pragma unroll
    for (int k = 10; k < 30; k++) {
        const float d = P[k] - T[k];
        cls += d * d;
    }

    return coo * (5.0f * loc + 2.0f * contain + ncl + cls)
         + 0.5f * noo * noobj;
}

__device__ __forceinline__ void load_cell(const float* __restrict__ src30,
                                          float* __restrict__ dst)
{
    const float2* s2 = reinterpret_cast<const float2*>(src30);
    float2 v[15];
    #pragma unroll
    for (int j = 0; j < 15; j++) v[j] = s2[j];
    #pragma unroll
    for (int j = 0; j < 15; j++) { dst[2 * j] = v[j].x; dst[2 * j + 1] = v[j].y; }
}

__global__ void __launch_bounds__(THREADS, 1) yolo_loss_kernel(
    const float* __restrict__ pred,
    const float* __restrict__ targ,
    int nfull, int rem, float inv_n,
    float* __restrict__ out)
{
    __shared__ __align__(8) unsigned long long full_bar[NSTAGES];
    __shared__ __align__(8) unsigned long long empty_bar[NSTAGES];
    __shared__ float warpsum[THREADS / 32];
    __shared__ bool  am_last;

    const int tid = threadIdx.x;
    const int wid = tid >> 5;
    const int lane = tid & 31;
    const long long G = gridDim.x;
    const char* pbytes = reinterpret_cast<const char*>(pred);
    const char* tbytes = reinterpret_cast<const char*>(targ);

    uint32_t fbar[NSTAGES], ebar[NSTAGES];
    #pragma unroll
    for (int s = 0; s < NSTAGES; s++) {
        fbar[s] = smem_u32(&full_bar[s]);
        ebar[s] = smem_u32(&empty_bar[s]);
    }
    const uint32_t stage0 = smem_u32(smem_buf);

    if (tid == 0) {
        #pragma unroll
        for (int s = 0; s < NSTAGES; s++) {
            mbar_init(fbar[s], 1);            // tx-based completion
            mbar_init(ebar[s], NCONS / 32);   // one arrive per consumer warp
        }
    }
    __syncthreads();

    float acc = 0.0f;

    if (wid == (NCONS / 32)) {
        // ---------- producer warp (lane 0 only) ----------
        if (lane == 0) {
            long long c = blockIdx.x;
            int k = 0;
            while (c < nfull) {
                const int s = k % NSTAGES;
                const uint32_t pphase = 1u ^ ((uint32_t)(k / NSTAGES) & 1u);
                mbar_wait_rlx(ebar[s], pphase);      // stage free?
                mbar_expect_tx(fbar[s], STAGE_BYTES);
                const uint32_t dst = stage0 + s * STAGE_BYTES;
                const char* psrc = pbytes + c * TENSOR_CHUNK_BYTES;
                const char* tsrc = tbytes + c * TENSOR_CHUNK_BYTES;
                // 4 x 15 KB: finer engine-level injection, same stage semantics
                bulk_cp(dst, psrc, HALF_TENSOR_BYTES, fbar[s]);
                bulk_cp(dst + HALF_TENSOR_BYTES, psrc + HALF_TENSOR_BYTES,
                        HALF_TENSOR_BYTES, fbar[s]);
                bulk_cp(dst + TENSOR_CHUNK_BYTES, tsrc, HALF_TENSOR_BYTES, fbar[s]);
                bulk_cp(dst + TENSOR_CHUNK_BYTES + HALF_TENSOR_BYTES,
                        tsrc + HALF_TENSOR_BYTES, HALF_TENSOR_BYTES, fbar[s]);
                c += G; k++;
            }
        }
    } else {
        // ---------- consumer warps ----------
        long long c = blockIdx.x;
        int k = 0;
        while (c < nfull) {
            const int s = k % NSTAGES;
            const uint32_t cphase = (uint32_t)(k / NSTAGES) & 1u;
            mbar_wait_acq(fbar[s], cphase);

            const float* stage = smem_buf + s * STAGE_FLOATS;
            float Pf[30], Tf[30];
            load_cell(stage + tid * 30, Pf);
            load_cell(stage + TENSOR_CHUNK_FLOATS + tid * 30, Tf);
            acc += cell_loss_reg(Pf, Tf);

            __syncwarp();
            if (lane == 0) mbar_arrive(ebar[s]);   // warp done with stage s
            c += G; k++;
        }

        // ragged tail (not hit for the benchmark shape)
        if (rem > 0 && blockIdx.x == 0 && tid < rem) {
            const long long cell = (long long)nfull * CPB + tid;
            float Pf[30], Tf[30];
            #pragma unroll
            for (int j = 0; j < 30; j++) {
                Pf[j] = __ldg(pred + cell * 30 + j);
                Tf[j] = __ldg(targ + cell * 30 + j);
            }
            acc += cell_loss_reg(Pf, Tf);
        }
    }

    // ---------- block reduction (producer warp contributes 0) ----------
    #pragma unroll
    for (int o = 16; o > 0; o >>= 1)
        acc += __shfl_down_sync(0xffffffffu, acc, o);
    if (lane == 0) warpsum[wid] = acc;
    __syncthreads();
    if (tid == 0) {
        float s = 0.0f;
        #pragma unroll
        for (int w = 0; w < THREADS / 32; w++) s += warpsum[w];
        g_partials[blockIdx.x] = s;
        __threadfence();
        const unsigned t = atomicAdd(&g_ticket, 1u);
        am_last = (t == gridDim.x - 1);
    }
    __syncthreads();

    // last block reduces all partials in fixed order (deterministic)
    if (am_last) {
        float s = 0.0f;
        for (int i = tid; i < (int)gridDim.x; i += THREADS)
            s += __ldcg(&g_partials[i]);
        #pragma unroll
        for (int o = 16; o > 0; o >>= 1)
            s += __shfl_down_sync(0xffffffffu, s, o);
        if (lane == 0) warpsum[wid] = s;
        __syncthreads();
        if (tid == 0) {
            float tot = 0.0f;
            #pragma unroll
            for (int w = 0; w < THREADS / 32; w++) tot += warpsum[w];
            out[0] = tot * inv_n;
            g_ticket = 0;   // reset for next graph replay
        }
    }
}

extern "C" void kernel_launch(void* const* d_in, const int* in_sizes, int n_in,
                              void* d_out, int out_size)
{
    const float* pred = (const float*)d_in[0];
    const float* targ = (const float*)d_in[1];
    const int total = in_sizes[0];   // N*14*14*30
    const int cells = total / 30;
    const int N = cells / 196;
    const int nfull = cells / CPB;
    const int rem = cells % CPB;

    cudaFuncSetAttribute(yolo_loss_kernel,
                         cudaFuncAttributeMaxDynamicSharedMemorySize, SMEM_BYTES);

    int sms = 148;
    cudaDeviceGetAttribute(&sms, cudaDevAttrMultiProcessorCount, 0);

    int grid = sms;                  // 1 CTA/SM (184 KB smem)
    if (grid > nfull) grid = (nfull > 0) ? nfull : 1;
    if (grid > MAX_BLOCKS) grid = MAX_BLOCKS;

    yolo_loss_kernel<<<grid, THREADS, SMEM_BYTES>>>(pred, targ, nfull, rem,
                                                    1.0f / (float)N,
                                                    (float*)d_out);
}

// round 17
// speedup vs baseline: 1.0251x; 1.0251x over previous
#include <cuda_runtime.h>
#include <cstdint>

#define NCONS 256                                  // consumer threads (8 warps)
#define THREADS (NCONS + 32)                       // + 1 producer warp = 288
#define CPB 196                                    // cells per chunk (one 14x14 image)
#define TENSOR_CHUNK_BYTES (CPB * 30 * 4)          // 23520
#define HALF_TENSOR_BYTES (TENSOR_CHUNK_BYTES / 2) // 11760
#define STAGE_BYTES (2 * TENSOR_CHUNK_BYTES)       // 47040 (pred + targ)
#define STAGE_FLOATS (STAGE_BYTES / 4)             // 11760
#define TENSOR_CHUNK_FLOATS (TENSOR_CHUNK_BYTES / 4)
#define NSTAGES 3
#define SMEM_BYTES (NSTAGES * STAGE_BYTES)         // 141120 -> 1 CTA/SM
#define MAX_BLOCKS 4096

__device__ float        g_partials[MAX_BLOCKS];
__device__ unsigned int g_ticket = 0;

extern __shared__ float smem_buf[];

__device__ __forceinline__ uint32_t smem_u32(const void* p) {
    return (uint32_t)__cvta_generic_to_shared(p);
}
__device__ __forceinline__ void mbar_init(uint32_t bar, uint32_t count) {
    asm volatile("mbarrier.init.shared.b64 [%0], %1;" :: "r"(bar), "r"(count) : "memory");
}
__device__ __forceinline__ void mbar_expect_tx(uint32_t bar, uint32_t bytes) {
    asm volatile("mbarrier.arrive.expect_tx.shared.b64 _, [%0], %1;"
                 :: "r"(bar), "r"(bytes) : "memory");
}
__device__ __forceinline__ void mbar_arrive(uint32_t bar) {
    asm volatile("mbarrier.arrive.release.cta.shared::cta.b64 _, [%0];"
                 :: "r"(bar) : "memory");
}
__device__ __forceinline__ void mbar_wait_acq(uint32_t bar, uint32_t phase) {
    uint32_t done;
    asm volatile(
        "{\n\t.reg .pred p;\n\t"
        "mbarrier.try_wait.parity.acquire.cta.shared::cta.b64 p, [%1], %2;\n\t"
        "selp.b32 %0, 1, 0, p;\n\t}"
        : "=r"(done) : "r"(bar), "r"(phase) : "memory");
    while (!done) {
        asm volatile(
            "{\n\t.reg .pred p;\n\t"
            "mbarrier.try_wait.parity.acquire.cta.shared::cta.b64 p, [%1], %2, 0x989680;\n\t"
            "selp.b32 %0, 1, 0, p;\n\t}"
            : "=r"(done) : "r"(bar), "r"(phase) : "memory");
    }
}
// Relaxed wait: producer only — its post-wait writes are async-proxy bulk copies.
__device__ __forceinline__ void mbar_wait_rlx(uint32_t bar, uint32_t phase) {
    uint32_t done;
    asm volatile(
        "{\n\t.reg .pred p;\n\t"
        "mbarrier.try_wait.parity.relaxed.cta.shared::cta.b64 p, [%1], %2, 0x989680;\n\t"
        "selp.b32 %0, 1, 0, p;\n\t}"
        : "=r"(done) : "r"(bar), "r"(phase) : "memory");
    while (!done) {
        asm volatile(
            "{\n\t.reg .pred p;\n\t"
            "mbarrier.try_wait.parity.relaxed.cta.shared::cta.b64 p, [%1], %2, 0x989680;\n\t"
            "selp.b32 %0, 1, 0, p;\n\t}"
            : "=r"(done) : "r"(bar), "r"(phase) : "memory");
    }
}
__device__ __forceinline__ void bulk_cp(uint32_t dst_smem, const void* src_gmem,
                                        uint32_t bytes, uint32_t bar) {
    asm volatile(
        "cp.async.bulk.shared::cluster.global.mbarrier::complete_tx::bytes "
        "[%0], [%1], %2, [%3];"
        :: "r"(dst_smem), "l"(src_gmem), "r"(bytes), "r"(bar) : "memory");
}

__device__ __forceinline__ float cell_loss_reg(const float* __restrict__ P,
                                               const float* __restrict__ T)
{
    const float inv14 = 1.0f / 14.0f;

    const float conf_t = T[4];
    const float coo = (conf_t > 0.0f) ? 1.0f : 0.0f;
    const float noo = (conf_t == 0.0f) ? 1.0f : 0.0f;

    const float tcx = T[0] * inv14;
    const float tcy = T[1] * inv14;
    const float tx1 = tcx - 0.5f * T[2];
    const float ty1 = tcy - 0.5f * T[3];
    const float tx2 = tcx + 0.5f * T[2];
    const float ty2 = tcy + 0.5f * T[3];
    const float ta = (tx2 - tx1) * (ty2 - ty1);

    float iou[2];
    #pragma unroll
    for (int b = 0; b < 2; b++) {
        const float* B = P + b * 5;
        const float pcx = B[0] * inv14;
        const float pcy = B[1] * inv14;
        const float px1 = pcx - 0.5f * B[2];
        const float py1 = pcy - 0.5f * B[3];
        const float px2 = pcx + 0.5f * B[2];
        const float py2 = pcy + 0.5f * B[3];
        const float ltx = fmaxf(px1, tx1);
        const float lty = fmaxf(py1, ty1);
        const float rbx = fminf(px2, tx2);
        const float rby = fminf(py2, ty2);
        const float w = fmaxf(rbx - ltx, 0.0f);
        const float h = fmaxf(rby - lty, 0.0f);
        const float inter = w * h;
        const float pa = (px2 - px1) * (py2 - py1);
        iou[b] = __fdividef(inter, pa + ta - inter);
    }

    const int r = (iou[1] > iou[0]) ? 1 : 0;   // argmax: first max wins
    const int ro = r * 5, nro = (1 - r) * 5;
    const float max_iou = (iou[1] > iou[0]) ? iou[1] : iou[0];

    const float dx = P[ro + 0] - T[0];
    const float dy = P[ro + 1] - T[1];
    const float dsw = sqrtf(P[ro + 2]) - sqrtf(T[2]);
    const float dsh = sqrtf(P[ro + 3]) - sqrtf(T[3]);
    const float loc = dx * dx + dy * dy + dsw * dsw + dsh * dsh;

    const float dcc = P[ro + 4] - max_iou;
    const float contain = dcc * dcc;
    const float ncl = P[nro + 4] * P[nro + 4];

    const float d4 = P[4] - T[4];
    const float d9 = P[9] - T[9];
    const float noobj = d4 * d4 + d9 * d9;

    float cls = 0.0f;
    #pragma unroll
    for (int k = 10; k < 30; k++) {
        const float d = P[k] - T[k];
        cls += d * d;
    }

    return coo * (5.0f * loc + 2.0f * contain + ncl + cls)
         + 0.5f * noo * noobj;
}

__device__ __forceinline__ void load_cell(const float* __restrict__ src30,
                                          float* __restrict__ dst)
{
    const float2* s2 = reinterpret_cast<const float2*>(src30);
    float2 v[15];
    #pragma unroll
    for (int j = 0; j < 15; j++) v[j] = s2[j];
    #pragma unroll
    for (int j = 0; j < 15; j++) { dst[2 * j] = v[j].x; dst[2 * j + 1] = v[j].y; }
}

__global__ void __launch_bounds__(THREADS, 1) yolo_loss_kernel(
    const float* __restrict__ pred,
    const float* __restrict__ targ,
    int nfull, int rem, float inv_n,
    float* __restrict__ out)
{
    __shared__ __align__(8) unsigned long long full_bar[NSTAGES];
    __shared__ __align__(8) unsigned long long empty_bar[NSTAGES];
    __shared__ float warpsum[THREADS / 32];
    __shared__ bool  am_last;

    const int tid = threadIdx.x;
    const int wid = tid >> 5;
    const int lane = tid & 31;
    const long long G = gridDim.x;
    const char* pbytes = reinterpret_cast<const char*>(pred);
    const char* tbytes = reinterpret_cast<const char*>(targ);

    uint32_t fbar[NSTAGES], ebar[NSTAGES];
    #pragma unroll
    for (int s = 0; s < NSTAGES; s++) {
        fbar[s] = smem_u32(&full_bar[s]);
        ebar[s] = smem_u32(&empty_bar[s]);
    }
    const uint32_t stage0 = smem_u32(smem_buf);

    if (tid == 0) {
        #pragma unroll
        for (int s = 0; s < NSTAGES; s++) {
            mbar_init(fbar[s], 1);            // tx-based completion
            mbar_init(ebar[s], NCONS / 32);   // one arrive per consumer warp
        }
    }
    __syncthreads();

    float acc = 0.0f;

    if (wid == (NCONS / 32)) {
        // ---------- producer warp (lane 0 only) ----------
        if (lane == 0) {
            long long c = blockIdx.x;
            int k = 0;
            while (c < nfull) {
                const int s = k % NSTAGES;
                const uint32_t pphase = 1u ^ ((uint32_t)(k / NSTAGES) & 1u);
                mbar_wait_rlx(ebar[s], pphase);      // stage free?
                mbar_expect_tx(fbar[s], STAGE_BYTES);
                const uint32_t dst = stage0 + s * STAGE_BYTES;
                const char* psrc = pbytes + c * TENSOR_CHUNK_BYTES;
                const char* tsrc = tbytes + c * TENSOR_CHUNK_BYTES;
                // 4 x ~11.5 KB: fine engine-level injection, same stage semantics
                bulk_cp(dst, psrc, HALF_TENSOR_BYTES, fbar[s]);
                bulk_cp(dst + HALF_TENSOR_BYTES, psrc + HALF_TENSOR_BYTES,
                        HALF_TENSOR_BYTES, fbar[s]);
                bulk_cp(dst + TENSOR_CHUNK_BYTES, tsrc, HALF_TENSOR_BYTES, fbar[s]);
                bulk_cp(dst + TENSOR_CHUNK_BYTES + HALF_TENSOR_BYTES,
                        tsrc + HALF_TENSOR_BYTES, HALF_TENSOR_BYTES, fbar[s]);
                c += G; k++;
            }
        }
    } else {
        // ---------- consumer warps (tid >= CPB idle through the protocol) ----------
        long long c = blockIdx.x;
        int k = 0;
        while (c < nfull) {
            const int s = k % NSTAGES;
            const uint32_t cphase = (uint32_t)(k / NSTAGES) & 1u;
            mbar_wait_acq(fbar[s], cphase);

            if (tid < CPB) {
                const float* stage = smem_buf + s * STAGE_FLOATS;
                float Pf[30], Tf[30];
                load_cell(stage + tid * 30, Pf);
                load_cell(stage + TENSOR_CHUNK_FLOATS + tid * 30, Tf);
                acc += cell_loss_reg(Pf, Tf);
            }

            __syncwarp();
            if (lane == 0) mbar_arrive(ebar[s]);   // warp done with stage s
            c += G; k++;
        }

        // ragged tail (not hit for the benchmark shape; rem < CPB <= NCONS)
        if (rem > 0 && blockIdx.x == 0 && tid < rem) {
            const long long cell = (long long)nfull * CPB + tid;
            float Pf[30], Tf[30];
            #pragma unroll
            for (int j = 0; j < 30; j++) {
                Pf[j] = __ldg(pred + cell * 30 + j);
                Tf[j] = __ldg(targ + cell * 30 + j);
            }
            acc += cell_loss_reg(Pf, Tf);
        }
    }

    // ---------- block reduction (producer warp contributes 0) ----------
    #pragma unroll
    for (int o = 16; o > 0; o >>= 1)
        acc += __shfl_down_sync(0xffffffffu, acc, o);
    if (lane == 0) warpsum[wid] = acc;
    __syncthreads();
    if (tid == 0) {
        float s = 0.0f;
        #pragma unroll
        for (int w = 0; w < THREADS / 32; w++) s += warpsum[w];
        g_partials[blockIdx.x] = s;
        __threadfence();
        const unsigned t = atomicAdd(&g_ticket, 1u);
        am_last = (t == gridDim.x - 1);
    }
    __syncthreads();

    // last block reduces all partials in fixed order (deterministic)
    if (am_last) {
        float s = 0.0f;
        for (int i = tid; i < (int)gridDim.x; i += THREADS)
            s += __ldcg(&g_partials[i]);
        #pragma unroll
        for (int o = 16; o > 0; o >>= 1)
            s += __shfl_down_sync(0xffffffffu, s, o);
        if (lane == 0) warpsum[wid] = s;
        __syncthreads();
        if (tid == 0) {
            float tot = 0.0f;
            #pragma unroll
            for (int w = 0; w < THREADS / 32; w++) tot += warpsum[w];
            out[0] = tot * inv_n;
            g_ticket = 0;   // reset for next graph replay
        }
    }
}

extern "C" void kernel_launch(void* const* d_in, const int* in_sizes, int n_in,
                              void* d_out, int out_size)
{
    const float* pred = (const float*)d_in[0];
    const float* targ = (const float*)d_in[1];
    const int total = in_sizes[0];   // N*14*14*30
    const int cells = total / 30;
    const int N = cells / 196;
    const int nfull = cells / CPB;   // 4096 for the benchmark shape
    const int rem = cells % CPB;     // 0 for the benchmark shape

    cudaFuncSetAttribute(yolo_loss_kernel,
                         cudaFuncAttributeMaxDynamicSharedMemorySize, SMEM_BYTES);

    int sms = 148;
    cudaDeviceGetAttribute(&sms, cudaDevAttrMultiProcessorCount, 0);

    int grid = sms;                  // 1 CTA/SM (141 KB smem)
    if (grid > nfull) grid = (nfull > 0) ? nfull : 1;
    if (grid > MAX_BLOCKS) grid = MAX_BLOCKS;

    yolo_loss_kernel<<<grid, THREADS, SMEM_BYTES>>>(pred, targ, nfull, rem,
                                                    1.0f / (float)N,
                                                    (float*)d_out);
}